// round 6
// baseline (speedup 1.0000x reference)
#include <cuda_runtime.h>
#include <cuda_bf16.h>
#include <math.h>

#define NN   50000
#define EE   600000
#define HH   128
#define INF  7
#define OUTF 4
#define NL   4

// ---------------- scratch (allocation-free: __device__ globals) ----------------
__device__ float g_zA[NN * HH];
__device__ float g_zB[NN * HH];
__device__ float g_agg[NN * HH];
__device__ int   g_deg[NN];
__device__ int   g_scan[NN];
__device__ int   g_rowptr[NN + 1];
__device__ int   g_fill[NN];
__device__ int   g_col[EE];
__device__ float g_invdeg[NN];
__device__ int   g_bsum[64];
__device__ int   g_boff[64];
__device__ float g_bnsum[HH];
__device__ float g_bnsq[HH];
__device__ float g_scale[HH];
__device__ float g_shift[HH];
__device__ int   g_is64;

// ---------------- packed f32x2 helpers ----------------
typedef unsigned long long u64;

__device__ __forceinline__ u64 dup2(float a) {
    u64 r;
    asm("mov.b64 %0, {%1, %1};" : "=l"(r) : "f"(a));
    return r;
}
__device__ __forceinline__ void ffma2(u64& acc, u64 a2, u64 w2) {
    asm("fma.rn.f32x2 %0, %1, %2, %0;" : "+l"(acc) : "l"(a2), "l"(w2));
}
__device__ __forceinline__ float2 unpack2(u64 v) {
    float2 f;
    asm("mov.b64 {%0, %1}, %2;" : "=f"(f.x), "=f"(f.y) : "l"(v));
    return f;
}

// ---------------- edge-index dtype probe ----------------
__global__ void k_detect(const int* __restrict__ ei32) {
    if (threadIdx.x == 0) {
        int z = 0;
#pragma unroll
        for (int i = 0; i < 16; i++) z |= ei32[2 * i + 1];
        g_is64 = (z == 0) ? 1 : 0;
    }
}

__device__ __forceinline__ int clampN(int v) {
    v = v < 0 ? 0 : v;
    return v >= NN ? NN - 1 : v;
}
__device__ __forceinline__ int edge_src(const void* ei, int e) {
    int v = g_is64 ? (int)((const long long*)ei)[e] : ((const int*)ei)[e];
    return clampN(v);
}
__device__ __forceinline__ int edge_dst(const void* ei, int e) {
    int v = g_is64 ? (int)((const long long*)ei)[EE + e] : ((const int*)ei)[EE + e];
    return clampN(v);
}

// ---------------- CSR build ----------------
__global__ void k_degree(const void* __restrict__ ei) {
    int e = blockIdx.x * blockDim.x + threadIdx.x;
    if (e < EE) atomicAdd(&g_deg[edge_dst(ei, e)], 1);
}

__global__ void k_scan1() {
    __shared__ int wsum[32];
    int i = blockIdx.x * 1024 + threadIdx.x;
    int v = (i < NN) ? g_deg[i] : 0;
    int lane = threadIdx.x & 31, wid = threadIdx.x >> 5;
    int x = v;
#pragma unroll
    for (int d = 1; d < 32; d <<= 1) {
        int y = __shfl_up_sync(0xFFFFFFFFu, x, d);
        if (lane >= d) x += y;
    }
    if (lane == 31) wsum[wid] = x;
    __syncthreads();
    if (wid == 0) {
        int s = wsum[lane];
#pragma unroll
        for (int d = 1; d < 32; d <<= 1) {
            int y = __shfl_up_sync(0xFFFFFFFFu, s, d);
            if (lane >= d) s += y;
        }
        wsum[lane] = s;
    }
    __syncthreads();
    int off = (wid > 0) ? wsum[wid - 1] : 0;
    int incl = x + off;
    if (i < NN) g_scan[i] = incl;
    if (threadIdx.x == 1023) g_bsum[blockIdx.x] = incl;
}

__global__ void k_scan2(int nblk) {
    int lane = threadIdx.x & 31;
    int i0 = 2 * lane, i1 = 2 * lane + 1;
    int a = (i0 < nblk) ? g_bsum[i0] : 0;
    int b = (i1 < nblk) ? g_bsum[i1] : 0;
    int s = a + b;
    int x = s;
#pragma unroll
    for (int d = 1; d < 32; d <<= 1) {
        int y = __shfl_up_sync(0xFFFFFFFFu, x, d);
        if (lane >= d) x += y;
    }
    int excl = x - s;
    if (i0 < nblk) g_boff[i0] = excl;
    if (i1 < nblk) g_boff[i1] = excl + a;
}

__global__ void k_scan3() {
    int i = blockIdx.x * blockDim.x + threadIdx.x;
    if (i < NN) {
        g_rowptr[i + 1] = g_scan[i] + g_boff[i >> 10];
        if (i == 0) g_rowptr[0] = 0;
        g_fill[i] = 0;
        int d = g_deg[i];
        g_invdeg[i] = 1.0f / (float)(d > 1 ? d : 1);
    }
}

__global__ void k_scatter(const void* __restrict__ ei) {
    int e = blockIdx.x * blockDim.x + threadIdx.x;
    if (e < EE) {
        int dst = edge_dst(ei, e);
        int src = edge_src(ei, e);
        int p = g_rowptr[dst] + atomicAdd(&g_fill[dst], 1);
        g_col[p] = src;
    }
}

// ---------------- encoder ----------------
__global__ void k_enc(const float* __restrict__ x, const float* __restrict__ eW,
                      const float* __restrict__ eb, float* __restrict__ z) {
    __shared__ float W[INF * HH];
    for (int i = threadIdx.x; i < INF * HH; i += blockDim.x) W[i] = eW[i];
    __syncthreads();
    int idx = blockIdx.x * blockDim.x + threadIdx.x;
    if (idx >= NN * HH) return;
    int n = idx >> 7, h = idx & 127;
    float s = eb[h];
    const float* xr = x + n * INF;
#pragma unroll
    for (int k = 0; k < INF; k++) s = fmaf(xr[k], W[k * HH + h], s);
    z[idx] = s;
}

// ---------------- aggregation: warp per node, CSR gather-mean ----------------
__global__ void k_agg(const float* __restrict__ zin, float* __restrict__ agg) {
    int w = (blockIdx.x * blockDim.x + threadIdx.x) >> 5;
    int lane = threadIdx.x & 31;
    if (w >= NN) return;
    int beg = g_rowptr[w], end = g_rowptr[w + 1];
    float4 acc = make_float4(0.f, 0.f, 0.f, 0.f);
    for (int j = beg; j < end; j++) {
        int s = g_col[j];
        float4 v = *(const float4*)&zin[s * HH + lane * 4];
        acc.x += v.x; acc.y += v.y; acc.z += v.z; acc.w += v.w;
    }
    float id = g_invdeg[w];
    acc.x *= id; acc.y *= id; acc.z *= id; acc.w *= id;
    *(float4*)&agg[w * HH + lane * 4] = acc;
}

// ---------------- GEMM v3: zout = agg @ Wl + zin @ Wr + b ------------------
// 128 threads/CTA, 2 CTAs/SM. Thread tile 8 rows x 8 cols.
// A transposed in smem (AsT[k][row]) -> 8 consecutive rows = 2 LDS.128,
// broadcast across the 16 lanes sharing a rowgroup. Each A value dup'd ONCE
// and reused across 4 FFMA2 col-pairs (MOV/FFMA2 ratio 0.5 vs 1.0 in R5).
#define BM 64
#define GT 128
__global__ void __launch_bounds__(GT, 2)
k_gemm(const float* __restrict__ agg, const float* __restrict__ zin,
       const float* __restrict__ Wl, const float* __restrict__ Wr,
       const float* __restrict__ bias, float* __restrict__ zout) {
    extern __shared__ float sm[];
    float* Ws  = sm;               // [128][128] 64KB
    float* AsT = sm + HH * HH;     // [128][64]  32KB (transposed: [k][row])
    const int t = threadIdx.x;
    const int cg = t & 15;         // 16 col groups x 8 cols
    const int rg = t >> 4;         // 8 row groups x 8 rows
    const int c0 = cg * 8;
    const int r0 = rg * 8;
    const int row0 = blockIdx.x * BM;

    u64 acc[8][4];                 // 8 rows x 4 col-pairs (8 cols)
#pragma unroll
    for (int r = 0; r < 8; r++)
#pragma unroll
        for (int c = 0; c < 4; c++) acc[r][c] = 0ULL;

#pragma unroll
    for (int s = 0; s < 2; s++) {
        const float* W = s ? Wr : Wl;
        const float* A = s ? zin : agg;
        // stage W [k][c] (float4, coalesced)
        for (int i = t; i < HH * HH / 4; i += GT)
            ((float4*)Ws)[i] = ((const float4*)W)[i];
        // stage A transposed: read A[row][k..k+3] float4, scatter to AsT[k][row]
        for (int i = t; i < BM * (HH / 4); i += GT) {
            int r = i & (BM - 1);          // row fastest -> conflict-free STS
            int k4 = i >> 6;               // 0..31
            int gr = row0 + r;
            float4 v = make_float4(0.f, 0.f, 0.f, 0.f);
            if (gr < NN) v = ((const float4*)(A + (size_t)gr * HH))[k4];
            AsT[(k4 * 4 + 0) * BM + r] = v.x;
            AsT[(k4 * 4 + 1) * BM + r] = v.y;
            AsT[(k4 * 4 + 2) * BM + r] = v.z;
            AsT[(k4 * 4 + 3) * BM + r] = v.w;
        }
        __syncthreads();
#pragma unroll 4
        for (int k = 0; k < HH; k++) {
            ulonglong2 wA = *(const ulonglong2*)&Ws[k * HH + c0];
            ulonglong2 wB = *(const ulonglong2*)&Ws[k * HH + c0 + 4];
            float4 a03 = *(const float4*)&AsT[k * BM + r0];
            float4 a47 = *(const float4*)&AsT[k * BM + r0 + 4];
            u64 d0 = dup2(a03.x), d1 = dup2(a03.y), d2 = dup2(a03.z), d3 = dup2(a03.w);
            u64 d4 = dup2(a47.x), d5 = dup2(a47.y), d6 = dup2(a47.z), d7 = dup2(a47.w);
            ffma2(acc[0][0], d0, wA.x); ffma2(acc[0][1], d0, wA.y); ffma2(acc[0][2], d0, wB.x); ffma2(acc[0][3], d0, wB.y);
            ffma2(acc[1][0], d1, wA.x); ffma2(acc[1][1], d1, wA.y); ffma2(acc[1][2], d1, wB.x); ffma2(acc[1][3], d1, wB.y);
            ffma2(acc[2][0], d2, wA.x); ffma2(acc[2][1], d2, wA.y); ffma2(acc[2][2], d2, wB.x); ffma2(acc[2][3], d2, wB.y);
            ffma2(acc[3][0], d3, wA.x); ffma2(acc[3][1], d3, wA.y); ffma2(acc[3][2], d3, wB.x); ffma2(acc[3][3], d3, wB.y);
            ffma2(acc[4][0], d4, wA.x); ffma2(acc[4][1], d4, wA.y); ffma2(acc[4][2], d4, wB.x); ffma2(acc[4][3], d4, wB.y);
            ffma2(acc[5][0], d5, wA.x); ffma2(acc[5][1], d5, wA.y); ffma2(acc[5][2], d5, wB.x); ffma2(acc[5][3], d5, wB.y);
            ffma2(acc[6][0], d6, wA.x); ffma2(acc[6][1], d6, wA.y); ffma2(acc[6][2], d6, wB.x); ffma2(acc[6][3], d6, wB.y);
            ffma2(acc[7][0], d7, wA.x); ffma2(acc[7][1], d7, wA.y); ffma2(acc[7][2], d7, wB.x); ffma2(acc[7][3], d7, wB.y);
        }
        __syncthreads();
    }

    float4 bb0 = *(const float4*)&bias[c0];
    float4 bb1 = *(const float4*)&bias[c0 + 4];
#pragma unroll
    for (int rr = 0; rr < 8; rr++) {
        int gr = row0 + r0 + rr;
        if (gr < NN) {
            float2 p0 = unpack2(acc[rr][0]);
            float2 p1 = unpack2(acc[rr][1]);
            float2 p2 = unpack2(acc[rr][2]);
            float2 p3 = unpack2(acc[rr][3]);
            float4 o0, o1;
            o0.x = p0.x + bb0.x; o0.y = p0.y + bb0.y; o0.z = p1.x + bb0.z; o0.w = p1.y + bb0.w;
            o1.x = p2.x + bb1.x; o1.y = p2.y + bb1.y; o1.z = p3.x + bb1.z; o1.w = p3.y + bb1.w;
            *(float4*)&zout[(size_t)gr * HH + c0]     = o0;
            *(float4*)&zout[(size_t)gr * HH + c0 + 4] = o1;
        }
    }
}

// ---------------- BatchNorm ----------------
__global__ void k_bnstats(const float* __restrict__ z) {
    int h = threadIdx.x;
    int r0 = blockIdx.x * 256;
    int rend = r0 + 256; if (rend > NN) rend = NN;
    float s = 0.f, ss = 0.f;
    for (int r = r0; r < rend; r++) {
        float v = z[r * HH + h];
        s += v; ss = fmaf(v, v, ss);
    }
    atomicAdd(&g_bnsum[h], s);
    atomicAdd(&g_bnsq[h], ss);
}

__global__ void k_bnfin(const float* __restrict__ gamma, const float* __restrict__ beta) {
    int h = threadIdx.x;
    float inv = 1.0f / (float)NN;
    float mu = g_bnsum[h] * inv;
    float var = g_bnsq[h] * inv - mu * mu;
    float sc = gamma[h] * rsqrtf(var + 1e-5f);
    g_scale[h] = sc;
    g_shift[h] = beta[h] - mu * sc;
}

__global__ void k_bnapply(float* __restrict__ z) {
    int i = blockIdx.x * blockDim.x + threadIdx.x;
    if (i >= NN * (HH / 4)) return;
    int h4 = i & 31;
    float4 v = ((float4*)z)[i];
    float4 sc = ((const float4*)g_scale)[h4];
    float4 sh = ((const float4*)g_shift)[h4];
    v.x = fmaxf(fmaf(v.x, sc.x, sh.x), 0.f);
    v.y = fmaxf(fmaf(v.y, sc.y, sh.y), 0.f);
    v.z = fmaxf(fmaf(v.z, sc.z, sh.z), 0.f);
    v.w = fmaxf(fmaf(v.w, sc.w, sh.w), 0.f);
    ((float4*)z)[i] = v;
}

// ---------------- decoder ----------------
__global__ void k_dec(const float* __restrict__ z, const float* __restrict__ dW,
                      const float* __restrict__ db, float* __restrict__ out) {
    __shared__ float W[HH * OUTF];
    for (int i = threadIdx.x; i < HH * OUTF; i += blockDim.x) W[i] = dW[i];
    __syncthreads();
    int w = (blockIdx.x * blockDim.x + threadIdx.x) >> 5;
    int lane = threadIdx.x & 31;
    if (w >= NN) return;
    float4 zv = *(const float4*)&z[w * HH + lane * 4];
    int h = lane * 4;
    float o0 = zv.x * W[h * 4 + 0] + zv.y * W[(h + 1) * 4 + 0] + zv.z * W[(h + 2) * 4 + 0] + zv.w * W[(h + 3) * 4 + 0];
    float o1 = zv.x * W[h * 4 + 1] + zv.y * W[(h + 1) * 4 + 1] + zv.z * W[(h + 2) * 4 + 1] + zv.w * W[(h + 3) * 4 + 1];
    float o2 = zv.x * W[h * 4 + 2] + zv.y * W[(h + 1) * 4 + 2] + zv.z * W[(h + 2) * 4 + 2] + zv.w * W[(h + 3) * 4 + 2];
    float o3 = zv.x * W[h * 4 + 3] + zv.y * W[(h + 1) * 4 + 3] + zv.z * W[(h + 2) * 4 + 3] + zv.w * W[(h + 3) * 4 + 3];
#pragma unroll
    for (int d = 16; d; d >>= 1) {
        o0 += __shfl_down_sync(0xFFFFFFFFu, o0, d);
        o1 += __shfl_down_sync(0xFFFFFFFFu, o1, d);
        o2 += __shfl_down_sync(0xFFFFFFFFu, o2, d);
        o3 += __shfl_down_sync(0xFFFFFFFFu, o3, d);
    }
    if (lane == 0) {
        float4 r;
        r.x = o0 + db[0]; r.y = o1 + db[1]; r.z = o2 + db[2]; r.w = o3 + db[3];
        *(float4*)&out[w * 4] = r;
    }
}

// ---------------- launch ----------------
extern "C" void kernel_launch(void* const* d_in, const int* in_sizes, int n_in,
                              void* d_out, int out_size) {
    const float* x      = (const float*)d_in[0];
    const float* enc_W  = (const float*)d_in[1];
    const float* enc_b  = (const float*)d_in[2];
    const float* Wl     = (const float*)d_in[3];
    const float* Wr     = (const float*)d_in[4];
    const float* b      = (const float*)d_in[5];
    const float* bng    = (const float*)d_in[6];
    const float* bnb    = (const float*)d_in[7];
    const float* dec_W  = (const float*)d_in[8];
    const float* dec_b  = (const float*)d_in[9];
    const void*  ei     = d_in[10];
    float* out = (float*)d_out;

    float *zA, *zB, *agg;
    void* p;
    cudaGetSymbolAddress(&p, g_zA);  zA  = (float*)p;
    cudaGetSymbolAddress(&p, g_zB);  zB  = (float*)p;
    cudaGetSymbolAddress(&p, g_agg); agg = (float*)p;
    void *pdeg, *pbnsum, *pbnsq;
    cudaGetSymbolAddress(&pdeg, g_deg);
    cudaGetSymbolAddress(&pbnsum, g_bnsum);
    cudaGetSymbolAddress(&pbnsq, g_bnsq);

    const size_t GEMM_SMEM = (size_t)(HH * HH + BM * HH) * sizeof(float); // 96 KB
    cudaFuncSetAttribute(k_gemm, cudaFuncAttributeMaxDynamicSharedMemorySize, (int)GEMM_SMEM);

    const int TB = 256;
    const int egrid = (EE + TB - 1) / TB;

    // CSR build
    k_detect<<<1, 32>>>((const int*)ei);
    cudaMemsetAsync(pdeg, 0, NN * sizeof(int));
    k_degree<<<egrid, TB>>>(ei);
    k_scan1<<<(NN + 1023) / 1024, 1024>>>();
    k_scan2<<<1, 32>>>((NN + 1023) / 1024);
    k_scan3<<<(NN + TB - 1) / TB, TB>>>();
    k_scatter<<<egrid, TB>>>(ei);

    // encoder
    k_enc<<<(NN * HH + TB - 1) / TB, TB>>>(x, enc_W, enc_b, zA);

    float* zin = zA;
    float* zout = zB;
    for (int i = 0; i < NL; i++) {
        k_agg<<<(NN * 32 + TB - 1) / TB, TB>>>(zin, agg);
        k_gemm<<<(NN + BM - 1) / BM, GT, GEMM_SMEM>>>(agg, zin,
                Wl + (size_t)i * HH * HH, Wr + (size_t)i * HH * HH,
                b + (size_t)i * HH, zout);
        if (i < NL - 1) {
            cudaMemsetAsync(pbnsum, 0, HH * sizeof(float));
            cudaMemsetAsync(pbnsq, 0, HH * sizeof(float));
            k_bnstats<<<(NN + 255) / 256, HH>>>(zout);
            k_bnfin<<<1, HH>>>(bng + (size_t)i * HH, bnb + (size_t)i * HH);
            k_bnapply<<<(NN * (HH / 4) + TB - 1) / TB, TB>>>(zout);
        }
        float* tmp = zin; zin = zout; zout = tmp;
    }

    k_dec<<<(NN * 32 + TB - 1) / TB, TB>>>(zin, dec_W, dec_b, out);
}

// round 8
// speedup vs baseline: 1.4295x; 1.4295x over previous
#include <cuda_runtime.h>
#include <cuda_bf16.h>
#include <math.h>
#include <stdint.h>

#define NN   50000
#define EE   600000
#define HH   128
#define INF  7
#define OUTF 4
#define NL   4
#define MT   128
#define NTILES ((NN + MT - 1) / MT)

// ---------------- scratch ----------------
__device__ float g_zA[NN * HH];
__device__ float g_zB[NN * HH];
__device__ __nv_bfloat16 g_aggh[NN * HH];
__device__ __nv_bfloat16 g_aggl[NN * HH];
__device__ __nv_bfloat16 g_zh[NN * HH];
__device__ __nv_bfloat16 g_zl[NN * HH];
__device__ __nv_bfloat16 g_Wth[2 * NL * HH * HH];   // [layer*2+which][n][k] (transposed)
__device__ __nv_bfloat16 g_Wtl[2 * NL * HH * HH];
__device__ int   g_deg[NN];
__device__ int   g_scan[NN];
__device__ int   g_rowptr[NN + 1];
__device__ int   g_fill[NN];
__device__ int   g_col[EE];
__device__ float g_invdeg[NN];
__device__ int   g_bsum[64];
__device__ int   g_boff[64];
__device__ float g_bnsum[HH];
__device__ float g_bnsq[HH];
__device__ float g_scale[HH];
__device__ float g_shift[HH];
__device__ int   g_is64;

__device__ __forceinline__ uint32_t smem_u32(const void* p) {
    uint32_t a;
    asm("{ .reg .u64 t; cvta.to.shared.u64 t, %1; cvt.u32.u64 %0, t; }" : "=r"(a) : "l"(p));
    return a;
}

// ---------------- warp-level tensor ops (baseline PTX, sm_80+) ----------------
__device__ __forceinline__ void ldsm4(uint32_t* r, uint32_t addr) {
    asm volatile("ldmatrix.sync.aligned.m8n8.x4.shared.b16 {%0,%1,%2,%3}, [%4];"
        : "=r"(r[0]), "=r"(r[1]), "=r"(r[2]), "=r"(r[3]) : "r"(addr));
}
__device__ __forceinline__ void mma16816(float* d, const uint32_t* a, const uint32_t* b) {
    asm volatile("mma.sync.aligned.m16n8k16.row.col.f32.bf16.bf16.f32 "
        "{%0,%1,%2,%3}, {%4,%5,%6,%7}, {%8,%9}, {%0,%1,%2,%3};"
        : "+f"(d[0]), "+f"(d[1]), "+f"(d[2]), "+f"(d[3])
        : "r"(a[0]), "r"(a[1]), "r"(a[2]), "r"(a[3]), "r"(b[0]), "r"(b[1]));
}

// ---------------- edge-index dtype probe ----------------
__global__ void k_detect(const int* __restrict__ ei32) {
    if (threadIdx.x == 0) {
        int z = 0;
#pragma unroll
        for (int i = 0; i < 16; i++) z |= ei32[2 * i + 1];
        g_is64 = (z == 0) ? 1 : 0;
    }
}
__device__ __forceinline__ int clampN(int v) {
    v = v < 0 ? 0 : v;
    return v >= NN ? NN - 1 : v;
}
__device__ __forceinline__ int edge_src(const void* ei, int e) {
    int v = g_is64 ? (int)((const long long*)ei)[e] : ((const int*)ei)[e];
    return clampN(v);
}
__device__ __forceinline__ int edge_dst(const void* ei, int e) {
    int v = g_is64 ? (int)((const long long*)ei)[EE + e] : ((const int*)ei)[EE + e];
    return clampN(v);
}

// ---------------- CSR build ----------------
__global__ void k_degree(const void* __restrict__ ei) {
    int e = blockIdx.x * blockDim.x + threadIdx.x;
    if (e < EE) atomicAdd(&g_deg[edge_dst(ei, e)], 1);
}
__global__ void k_scan1() {
    __shared__ int wsum[32];
    int i = blockIdx.x * 1024 + threadIdx.x;
    int v = (i < NN) ? g_deg[i] : 0;
    int lane = threadIdx.x & 31, wid = threadIdx.x >> 5;
    int x = v;
#pragma unroll
    for (int d = 1; d < 32; d <<= 1) {
        int y = __shfl_up_sync(0xFFFFFFFFu, x, d);
        if (lane >= d) x += y;
    }
    if (lane == 31) wsum[wid] = x;
    __syncthreads();
    if (wid == 0) {
        int s = wsum[lane];
#pragma unroll
        for (int d = 1; d < 32; d <<= 1) {
            int y = __shfl_up_sync(0xFFFFFFFFu, s, d);
            if (lane >= d) s += y;
        }
        wsum[lane] = s;
    }
    __syncthreads();
    int off = (wid > 0) ? wsum[wid - 1] : 0;
    int incl = x + off;
    if (i < NN) g_scan[i] = incl;
    if (threadIdx.x == 1023) g_bsum[blockIdx.x] = incl;
}
__global__ void k_scan2(int nblk) {
    int lane = threadIdx.x & 31;
    int i0 = 2 * lane, i1 = 2 * lane + 1;
    int a = (i0 < nblk) ? g_bsum[i0] : 0;
    int b = (i1 < nblk) ? g_bsum[i1] : 0;
    int s = a + b;
    int x = s;
#pragma unroll
    for (int d = 1; d < 32; d <<= 1) {
        int y = __shfl_up_sync(0xFFFFFFFFu, x, d);
        if (lane >= d) x += y;
    }
    int excl = x - s;
    if (i0 < nblk) g_boff[i0] = excl;
    if (i1 < nblk) g_boff[i1] = excl + a;
}
__global__ void k_scan3() {
    int i = blockIdx.x * blockDim.x + threadIdx.x;
    if (i < NN) {
        g_rowptr[i + 1] = g_scan[i] + g_boff[i >> 10];
        if (i == 0) g_rowptr[0] = 0;
        g_fill[i] = 0;
        int d = g_deg[i];
        g_invdeg[i] = 1.0f / (float)(d > 1 ? d : 1);
    }
}
__global__ void k_scatter(const void* __restrict__ ei) {
    int e = blockIdx.x * blockDim.x + threadIdx.x;
    if (e < EE) {
        int dst = edge_dst(ei, e);
        int src = edge_src(ei, e);
        int p = g_rowptr[dst] + atomicAdd(&g_fill[dst], 1);
        g_col[p] = src;
    }
}

// ---------------- W transpose + bf16 split (once per launch) ----------------
__global__ void k_wconv(const float* __restrict__ Wl, const float* __restrict__ Wr) {
    int idx = blockIdx.x * blockDim.x + threadIdx.x;
    if (idx >= 2 * NL * HH * HH) return;
    int m2 = idx / (HH * HH);
    int rem = idx - m2 * (HH * HH);
    int n = rem >> 7, k = rem & 127;
    int layer = m2 >> 1;
    const float* src = (m2 & 1) ? Wr : Wl;
    float v = src[layer * HH * HH + k * HH + n];      // B[n][k] = W[k][n]
    __nv_bfloat16 hi = __float2bfloat16_rn(v);
    __nv_bfloat16 lo = __float2bfloat16_rn(v - __bfloat162float(hi));
    g_Wth[m2 * HH * HH + n * HH + k] = hi;
    g_Wtl[m2 * HH * HH + n * HH + k] = lo;
}

// ---------------- encoder (emits fp32 z + bf16 hi/lo) ----------------
__global__ void k_enc(const float* __restrict__ x, const float* __restrict__ eW,
                      const float* __restrict__ eb, float* __restrict__ z) {
    __shared__ float W[INF * HH];
    for (int i = threadIdx.x; i < INF * HH; i += blockDim.x) W[i] = eW[i];
    __syncthreads();
    int idx = blockIdx.x * blockDim.x + threadIdx.x;
    if (idx >= NN * HH) return;
    int n = idx >> 7, h = idx & 127;
    float s = eb[h];
    const float* xr = x + n * INF;
#pragma unroll
    for (int k = 0; k < INF; k++) s = fmaf(xr[k], W[k * HH + h], s);
    z[idx] = s;
    __nv_bfloat16 hi = __float2bfloat16_rn(s);
    g_zh[idx] = hi;
    g_zl[idx] = __float2bfloat16_rn(s - __bfloat162float(hi));
}

// ---------------- aggregation (emits bf16 hi/lo agg) ----------------
__global__ void k_agg(const float* __restrict__ zin) {
    int w = (blockIdx.x * blockDim.x + threadIdx.x) >> 5;
    int lane = threadIdx.x & 31;
    if (w >= NN) return;
    int beg = g_rowptr[w], end = g_rowptr[w + 1];
    float4 acc = make_float4(0.f, 0.f, 0.f, 0.f);
    for (int j = beg; j < end; j++) {
        int s = g_col[j];
        float4 v = *(const float4*)&zin[s * HH + lane * 4];
        acc.x += v.x; acc.y += v.y; acc.z += v.z; acc.w += v.w;
    }
    float id = g_invdeg[w];
    acc.x *= id; acc.y *= id; acc.z *= id; acc.w *= id;
    __nv_bfloat162 hA = __floats2bfloat162_rn(acc.x, acc.y);
    __nv_bfloat162 hB = __floats2bfloat162_rn(acc.z, acc.w);
    __nv_bfloat162 lA = __floats2bfloat162_rn(acc.x - __low2float(hA), acc.y - __high2float(hA));
    __nv_bfloat162 lB = __floats2bfloat162_rn(acc.z - __low2float(hB), acc.w - __high2float(hB));
    uint2 ph, pl;
    ph.x = *(uint32_t*)&hA; ph.y = *(uint32_t*)&hB;
    pl.x = *(uint32_t*)&lA; pl.y = *(uint32_t*)&lB;
    *(uint2*)&g_aggh[w * HH + lane * 4] = ph;
    *(uint2*)&g_aggl[w * HH + lane * 4] = pl;
}

// ---------------- HMMA GEMM: zout = agg@Wl + z@Wr + b -----------------------
// 128x128 tile per CTA, 256 threads (8 warps: 4 m-groups x 2 n-groups).
// fp32 = hi+lo bf16 split; D += Ah*Bh + Ah*Bl + Al*Bh (lo*lo dropped ~2^-16).
// smem tiles swizzled: 16B chunk index XOR (row&7) -> conflict-free ldmatrix.
#define SM_A_H 0
#define SM_A_L 32768
#define SM_B_H 65536
#define SM_B_L 98304
#define GEMM_SMEM 131072

__device__ __forceinline__ void stage_tile(char* smb, int off, const __nv_bfloat16* src,
                                           int row0, int t, int guard) {
    for (int i = t; i < 2048; i += 256) {
        int row = i >> 4, ch = i & 15;
        int gr = row0 + row;
        uint4 v = make_uint4(0, 0, 0, 0);
        if (!guard || gr < NN) v = *(const uint4*)(src + (size_t)gr * HH + ch * 8);
        *(uint4*)(smb + off + row * 256 + (ch ^ (row & 7)) * 16) = v;
    }
}

__global__ void __launch_bounds__(256, 1)
k_gemm_mma(const __nv_bfloat16* __restrict__ wlh, const __nv_bfloat16* __restrict__ wll,
           const __nv_bfloat16* __restrict__ wrh, const __nv_bfloat16* __restrict__ wrl,
           const float* __restrict__ bias, float* __restrict__ zout) {
    extern __shared__ char smb[];
    uint32_t sb = smem_u32(smb);
    const int t = threadIdx.x, wid = t >> 5, lane = t & 31;
    const int warp_m = wid & 3, warp_n = wid >> 2;
    const int m0 = warp_m * 32;          // 32 rows per warp
    const int n0 = warp_n * 64;          // 64 cols per warp
    const int row0 = blockIdx.x * MT;
    const int g = lane >> 2, tid4 = lane & 3;

    float d[2][8][4];
#pragma unroll
    for (int mt = 0; mt < 2; mt++)
#pragma unroll
        for (int nt = 0; nt < 8; nt++)
#pragma unroll
            for (int j = 0; j < 4; j++) d[mt][nt][j] = 0.f;

    // precomputed ldmatrix lane addresses (row, chunk base) for A and B
    const int a_row = (lane & 15);           // + m0 + mt*16
    const int a_chd = (lane >> 4);           // chunk delta 0/1
    const int b_row = (lane & 7) + ((lane >> 4) << 3);   // + n0 + np*16
    const int b_chd = (lane >> 3) & 1;

#pragma unroll
    for (int s = 0; s < 2; s++) {
        stage_tile(smb, SM_A_H, s ? g_zh : g_aggh, row0, t, 1);
        stage_tile(smb, SM_A_L, s ? g_zl : g_aggl, row0, t, 1);
        stage_tile(smb, SM_B_H, s ? wrh : wlh, 0, t, 0);
        stage_tile(smb, SM_B_L, s ? wrl : wll, 0, t, 0);
        __syncthreads();
#pragma unroll
        for (int ks = 0; ks < 8; ks++) {
            int c = ks * 2;
            uint32_t ah[2][4], al[2][4], bh[4][4], bl[4][4];
#pragma unroll
            for (int mt = 0; mt < 2; mt++) {
                int row = m0 + mt * 16 + a_row;
                int ch = c + a_chd;
                uint32_t o = (uint32_t)(row * 256 + (ch ^ (row & 7)) * 16);
                ldsm4(ah[mt], sb + SM_A_H + o);
                ldsm4(al[mt], sb + SM_A_L + o);
            }
#pragma unroll
            for (int np = 0; np < 4; np++) {
                int row = n0 + np * 16 + b_row;
                int ch = c + b_chd;
                uint32_t o = (uint32_t)(row * 256 + (ch ^ (row & 7)) * 16);
                ldsm4(bh[np], sb + SM_B_H + o);
                ldsm4(bl[np], sb + SM_B_L + o);
            }
#pragma unroll
            for (int mt = 0; mt < 2; mt++)
#pragma unroll
                for (int nt = 0; nt < 8; nt++) {
                    const uint32_t* fh = &bh[nt >> 1][(nt & 1) * 2];
                    const uint32_t* fl = &bl[nt >> 1][(nt & 1) * 2];
                    mma16816(d[mt][nt], ah[mt], fh);   // hi*hi
                    mma16816(d[mt][nt], ah[mt], fl);   // hi*lo
                    mma16816(d[mt][nt], al[mt], fh);   // lo*hi
                }
        }
        __syncthreads();
    }

    // epilogue: D fragment (16x8): d0=(g, tid*2) d1=(g, tid*2+1) d2=(g+8,..) d3
#pragma unroll
    for (int mt = 0; mt < 2; mt++) {
        int r_up = row0 + m0 + mt * 16 + g;
        int r_dn = r_up + 8;
#pragma unroll
        for (int nt = 0; nt < 8; nt++) {
            int cc = n0 + nt * 8 + tid4 * 2;
            float b0 = bias[cc], b1 = bias[cc + 1];
            if (r_up < NN) {
                float2 o = make_float2(d[mt][nt][0] + b0, d[mt][nt][1] + b1);
                *(float2*)&zout[(size_t)r_up * HH + cc] = o;
            }
            if (r_dn < NN) {
                float2 o = make_float2(d[mt][nt][2] + b0, d[mt][nt][3] + b1);
                *(float2*)&zout[(size_t)r_dn * HH + cc] = o;
            }
        }
    }
}

// ---------------- BatchNorm ----------------
__global__ void k_bnstats(const float* __restrict__ z) {
    int h = threadIdx.x;
    int r0 = blockIdx.x * 256;
    int rend = r0 + 256; if (rend > NN) rend = NN;
    float s = 0.f, ss = 0.f;
    for (int r = r0; r < rend; r++) {
        float v = z[r * HH + h];
        s += v; ss = fmaf(v, v, ss);
    }
    atomicAdd(&g_bnsum[h], s);
    atomicAdd(&g_bnsq[h], ss);
}
__global__ void k_bnfin(const float* __restrict__ gamma, const float* __restrict__ beta) {
    int h = threadIdx.x;
    float inv = 1.0f / (float)NN;
    float mu = g_bnsum[h] * inv;
    float var = g_bnsq[h] * inv - mu * mu;
    float sc = gamma[h] * rsqrtf(var + 1e-5f);
    g_scale[h] = sc;
    g_shift[h] = beta[h] - mu * sc;
}
// BN + ReLU in place, also emit bf16 hi/lo of the result
__global__ void k_bnapply(float* __restrict__ z) {
    int i = blockIdx.x * blockDim.x + threadIdx.x;
    if (i >= NN * (HH / 4)) return;
    int h4 = i & 31;
    float4 v = ((float4*)z)[i];
    float4 sc = ((const float4*)g_scale)[h4];
    float4 sh = ((const float4*)g_shift)[h4];
    v.x = fmaxf(fmaf(v.x, sc.x, sh.x), 0.f);
    v.y = fmaxf(fmaf(v.y, sc.y, sh.y), 0.f);
    v.z = fmaxf(fmaf(v.z, sc.z, sh.z), 0.f);
    v.w = fmaxf(fmaf(v.w, sc.w, sh.w), 0.f);
    ((float4*)z)[i] = v;
    __nv_bfloat162 hA = __floats2bfloat162_rn(v.x, v.y);
    __nv_bfloat162 hB = __floats2bfloat162_rn(v.z, v.w);
    __nv_bfloat162 lA = __floats2bfloat162_rn(v.x - __low2float(hA), v.y - __high2float(hA));
    __nv_bfloat162 lB = __floats2bfloat162_rn(v.z - __low2float(hB), v.w - __high2float(hB));
    uint2 ph, pl;
    ph.x = *(uint32_t*)&hA; ph.y = *(uint32_t*)&hB;
    pl.x = *(uint32_t*)&lA; pl.y = *(uint32_t*)&lB;
    *(uint2*)&g_zh[i * 4] = ph;
    *(uint2*)&g_zl[i * 4] = pl;
}

// ---------------- decoder ----------------
__global__ void k_dec(const float* __restrict__ z, const float* __restrict__ dW,
                      const float* __restrict__ db, float* __restrict__ out) {
    __shared__ float W[HH * OUTF];
    for (int i = threadIdx.x; i < HH * OUTF; i += blockDim.x) W[i] = dW[i];
    __syncthreads();
    int w = (blockIdx.x * blockDim.x + threadIdx.x) >> 5;
    int lane = threadIdx.x & 31;
    if (w >= NN) return;
    float4 zv = *(const float4*)&z[w * HH + lane * 4];
    int h = lane * 4;
    float o0 = zv.x * W[h * 4 + 0] + zv.y * W[(h + 1) * 4 + 0] + zv.z * W[(h + 2) * 4 + 0] + zv.w * W[(h + 3) * 4 + 0];
    float o1 = zv.x * W[h * 4 + 1] + zv.y * W[(h + 1) * 4 + 1] + zv.z * W[(h + 2) * 4 + 1] + zv.w * W[(h + 3) * 4 + 1];
    float o2 = zv.x * W[h * 4 + 2] + zv.y * W[(h + 1) * 4 + 2] + zv.z * W[(h + 2) * 4 + 2] + zv.w * W[(h + 3) * 4 + 2];
    float o3 = zv.x * W[h * 4 + 3] + zv.y * W[(h + 1) * 4 + 3] + zv.z * W[(h + 2) * 4 + 3] + zv.w * W[(h + 3) * 4 + 3];
#pragma unroll
    for (int d = 16; d; d >>= 1) {
        o0 += __shfl_down_sync(0xFFFFFFFFu, o0, d);
        o1 += __shfl_down_sync(0xFFFFFFFFu, o1, d);
        o2 += __shfl_down_sync(0xFFFFFFFFu, o2, d);
        o3 += __shfl_down_sync(0xFFFFFFFFu, o3, d);
    }
    if (lane == 0) {
        float4 r;
        r.x = o0 + db[0]; r.y = o1 + db[1]; r.z = o2 + db[2]; r.w = o3 + db[3];
        *(float4*)&out[w * 4] = r;
    }
}

// ---------------- launch ----------------
extern "C" void kernel_launch(void* const* d_in, const int* in_sizes, int n_in,
                              void* d_out, int out_size) {
    const float* x      = (const float*)d_in[0];
    const float* enc_W  = (const float*)d_in[1];
    const float* enc_b  = (const float*)d_in[2];
    const float* Wl     = (const float*)d_in[3];
    const float* Wr     = (const float*)d_in[4];
    const float* b      = (const float*)d_in[5];
    const float* bng    = (const float*)d_in[6];
    const float* bnb    = (const float*)d_in[7];
    const float* dec_W  = (const float*)d_in[8];
    const float* dec_b  = (const float*)d_in[9];
    const void*  ei     = d_in[10];
    float* out = (float*)d_out;

    float *zA, *zB;
    __nv_bfloat16 *Wth, *Wtl;
    void* p;
    cudaGetSymbolAddress(&p, g_zA);  zA  = (float*)p;
    cudaGetSymbolAddress(&p, g_zB);  zB  = (float*)p;
    cudaGetSymbolAddress(&p, g_Wth); Wth = (__nv_bfloat16*)p;
    cudaGetSymbolAddress(&p, g_Wtl); Wtl = (__nv_bfloat16*)p;
    void *pdeg, *pbnsum, *pbnsq;
    cudaGetSymbolAddress(&pdeg, g_deg);
    cudaGetSymbolAddress(&pbnsum, g_bnsum);
    cudaGetSymbolAddress(&pbnsq, g_bnsq);

    cudaFuncSetAttribute(k_gemm_mma, cudaFuncAttributeMaxDynamicSharedMemorySize, GEMM_SMEM);

    const int TB = 256;
    const int egrid = (EE + TB - 1) / TB;

    // CSR build + W conversion
    k_detect<<<1, 32>>>((const int*)ei);
    cudaMemsetAsync(pdeg, 0, NN * sizeof(int));
    k_degree<<<egrid, TB>>>(ei);
    k_scan1<<<(NN + 1023) / 1024, 1024>>>();
    k_scan2<<<1, 32>>>((NN + 1023) / 1024);
    k_scan3<<<(NN + TB - 1) / TB, TB>>>();
    k_scatter<<<egrid, TB>>>(ei);
    k_wconv<<<(2 * NL * HH * HH + TB - 1) / TB, TB>>>(Wl, Wr);

    k_enc<<<(NN * HH + TB - 1) / TB, TB>>>(x, enc_W, enc_b, zA);

    float* zin = zA;
    float* zout = zB;
    for (int i = 0; i < NL; i++) {
        k_agg<<<(NN * 32 + TB - 1) / TB, TB>>>(zin);
        k_gemm_mma<<<NTILES, 256, GEMM_SMEM>>>(
            Wth + (size_t)(2 * i + 0) * HH * HH, Wtl + (size_t)(2 * i + 0) * HH * HH,
            Wth + (size_t)(2 * i + 1) * HH * HH, Wtl + (size_t)(2 * i + 1) * HH * HH,
            b + (size_t)i * HH, zout);
        if (i < NL - 1) {
            cudaMemsetAsync(pbnsum, 0, HH * sizeof(float));
            cudaMemsetAsync(pbnsq, 0, HH * sizeof(float));
            k_bnstats<<<(NN + 255) / 256, HH>>>(zout);
            k_bnfin<<<1, HH>>>(bng + (size_t)i * HH, bnb + (size_t)i * HH);
            k_bnapply<<<(NN * (HH / 4) + TB - 1) / TB, TB>>>(zout);
        }
        float* tmp = zin; zin = zout; zout = tmp;
    }

    k_dec<<<(NN * 32 + TB - 1) / TB, TB>>>(zin, dec_W, dec_b, out);
}

// round 9
// speedup vs baseline: 1.6501x; 1.1543x over previous
#include <cuda_runtime.h>
#include <cuda_bf16.h>
#include <math.h>
#include <stdint.h>

#define NN   50000
#define EE   600000
#define HH   128
#define INF  7
#define OUTF 4
#define NL   4
#define MT   128
#define NTILES ((NN + MT - 1) / MT)

// ---------------- scratch ----------------
__device__ float g_zA[NN * HH];
__device__ float g_zB[NN * HH];
__device__ __nv_bfloat16 g_aggh[NN * HH];
__device__ __nv_bfloat16 g_aggl[NN * HH];
__device__ __nv_bfloat16 g_zh[NN * HH];
__device__ __nv_bfloat16 g_zl[NN * HH];
__device__ __nv_bfloat16 g_Wth[2 * NL * HH * HH];   // [layer*2+which][n][k] (transposed)
__device__ __nv_bfloat16 g_Wtl[2 * NL * HH * HH];
__device__ int   g_deg[NN];
__device__ int   g_scan[NN];
__device__ int   g_rowptr[NN + 1];
__device__ int   g_fill[NN];
__device__ int   g_col[EE];
__device__ float g_invdeg[NN];
__device__ int   g_bsum[64];
__device__ int   g_boff[64];
__device__ float g_bnsum[HH];
__device__ float g_bnsq[HH];
__device__ float g_scale[HH];
__device__ float g_shift[HH];
__device__ int   g_is64;

__device__ __forceinline__ uint32_t smem_u32(const void* p) {
    uint32_t a;
    asm("{ .reg .u64 t; cvta.to.shared.u64 t, %1; cvt.u32.u64 %0, t; }" : "=r"(a) : "l"(p));
    return a;
}

// ---------------- warp-level tensor ops (baseline PTX, sm_80+) ----------------
__device__ __forceinline__ void ldsm4(uint32_t* r, uint32_t addr) {
    asm volatile("ldmatrix.sync.aligned.m8n8.x4.shared.b16 {%0,%1,%2,%3}, [%4];"
        : "=r"(r[0]), "=r"(r[1]), "=r"(r[2]), "=r"(r[3]) : "r"(addr));
}
__device__ __forceinline__ void mma16816(float* d, const uint32_t* a, const uint32_t* b) {
    asm volatile("mma.sync.aligned.m16n8k16.row.col.f32.bf16.bf16.f32 "
        "{%0,%1,%2,%3}, {%4,%5,%6,%7}, {%8,%9}, {%0,%1,%2,%3};"
        : "+f"(d[0]), "+f"(d[1]), "+f"(d[2]), "+f"(d[3])
        : "r"(a[0]), "r"(a[1]), "r"(a[2]), "r"(a[3]), "r"(b[0]), "r"(b[1]));
}

// ---------------- edge-index dtype probe ----------------
__global__ void k_detect(const int* __restrict__ ei32) {
    if (threadIdx.x == 0) {
        int z = 0;
#pragma unroll
        for (int i = 0; i < 16; i++) z |= ei32[2 * i + 1];
        g_is64 = (z == 0) ? 1 : 0;
    }
}
__device__ __forceinline__ int clampN(int v) {
    v = v < 0 ? 0 : v;
    return v >= NN ? NN - 1 : v;
}
__device__ __forceinline__ int edge_src(const void* ei, int e) {
    int v = g_is64 ? (int)((const long long*)ei)[e] : ((const int*)ei)[e];
    return clampN(v);
}
__device__ __forceinline__ int edge_dst(const void* ei, int e) {
    int v = g_is64 ? (int)((const long long*)ei)[EE + e] : ((const int*)ei)[EE + e];
    return clampN(v);
}

// ---------------- CSR build ----------------
__global__ void k_degree(const void* __restrict__ ei) {
    int e = blockIdx.x * blockDim.x + threadIdx.x;
    if (e < EE) atomicAdd(&g_deg[edge_dst(ei, e)], 1);
}
__global__ void k_scan1() {
    __shared__ int wsum[32];
    int i = blockIdx.x * 1024 + threadIdx.x;
    int v = (i < NN) ? g_deg[i] : 0;
    int lane = threadIdx.x & 31, wid = threadIdx.x >> 5;
    int x = v;
#pragma unroll
    for (int d = 1; d < 32; d <<= 1) {
        int y = __shfl_up_sync(0xFFFFFFFFu, x, d);
        if (lane >= d) x += y;
    }
    if (lane == 31) wsum[wid] = x;
    __syncthreads();
    if (wid == 0) {
        int s = wsum[lane];
#pragma unroll
        for (int d = 1; d < 32; d <<= 1) {
            int y = __shfl_up_sync(0xFFFFFFFFu, s, d);
            if (lane >= d) s += y;
        }
        wsum[lane] = s;
    }
    __syncthreads();
    int off = (wid > 0) ? wsum[wid - 1] : 0;
    int incl = x + off;
    if (i < NN) g_scan[i] = incl;
    if (threadIdx.x == 1023) g_bsum[blockIdx.x] = incl;
}
__global__ void k_scan2(int nblk) {
    int lane = threadIdx.x & 31;
    int i0 = 2 * lane, i1 = 2 * lane + 1;
    int a = (i0 < nblk) ? g_bsum[i0] : 0;
    int b = (i1 < nblk) ? g_bsum[i1] : 0;
    int s = a + b;
    int x = s;
#pragma unroll
    for (int d = 1; d < 32; d <<= 1) {
        int y = __shfl_up_sync(0xFFFFFFFFu, x, d);
        if (lane >= d) x += y;
    }
    int excl = x - s;
    if (i0 < nblk) g_boff[i0] = excl;
    if (i1 < nblk) g_boff[i1] = excl + a;
}
__global__ void k_scan3() {
    int i = blockIdx.x * blockDim.x + threadIdx.x;
    if (i < NN) {
        g_rowptr[i + 1] = g_scan[i] + g_boff[i >> 10];
        if (i == 0) g_rowptr[0] = 0;
        g_fill[i] = 0;
        int d = g_deg[i];
        g_invdeg[i] = 1.0f / (float)(d > 1 ? d : 1);
    }
}
__global__ void k_scatter(const void* __restrict__ ei) {
    int e = blockIdx.x * blockDim.x + threadIdx.x;
    if (e < EE) {
        int dst = edge_dst(ei, e);
        int src = edge_src(ei, e);
        int p = g_rowptr[dst] + atomicAdd(&g_fill[dst], 1);
        g_col[p] = src;
    }
}

// ---------------- W transpose + bf16 split (once per launch) ----------------
__global__ void k_wconv(const float* __restrict__ Wl, const float* __restrict__ Wr) {
    int idx = blockIdx.x * blockDim.x + threadIdx.x;
    if (idx >= 2 * NL * HH * HH) return;
    int m2 = idx / (HH * HH);
    int rem = idx - m2 * (HH * HH);
    int n = rem >> 7, k = rem & 127;
    int layer = m2 >> 1;
    const float* src = (m2 & 1) ? Wr : Wl;
    float v = src[layer * HH * HH + k * HH + n];      // B[n][k] = W[k][n]
    __nv_bfloat16 hi = __float2bfloat16_rn(v);
    __nv_bfloat16 lo = __float2bfloat16_rn(v - __bfloat162float(hi));
    g_Wth[m2 * HH * HH + n * HH + k] = hi;
    g_Wtl[m2 * HH * HH + n * HH + k] = lo;
}

// ---------------- encoder (emits fp32 z + bf16 hi/lo) ----------------
__global__ void k_enc(const float* __restrict__ x, const float* __restrict__ eW,
                      const float* __restrict__ eb, float* __restrict__ z) {
    __shared__ float W[INF * HH];
    for (int i = threadIdx.x; i < INF * HH; i += blockDim.x) W[i] = eW[i];
    __syncthreads();
    int idx = blockIdx.x * blockDim.x + threadIdx.x;
    if (idx >= NN * HH) return;
    int n = idx >> 7, h = idx & 127;
    float s = eb[h];
    const float* xr = x + n * INF;
#pragma unroll
    for (int k = 0; k < INF; k++) s = fmaf(xr[k], W[k * HH + h], s);
    z[idx] = s;
    __nv_bfloat16 hi = __float2bfloat16_rn(s);
    g_zh[idx] = hi;
    g_zl[idx] = __float2bfloat16_rn(s - __bfloat162float(hi));
}

// ---------------- aggregation (emits bf16 hi/lo agg) ----------------
__global__ void k_agg(const float* __restrict__ zin) {
    int w = (blockIdx.x * blockDim.x + threadIdx.x) >> 5;
    int lane = threadIdx.x & 31;
    if (w >= NN) return;
    int beg = g_rowptr[w], end = g_rowptr[w + 1];
    float4 acc = make_float4(0.f, 0.f, 0.f, 0.f);
    for (int j = beg; j < end; j++) {
        int s = g_col[j];
        float4 v = *(const float4*)&zin[s * HH + lane * 4];
        acc.x += v.x; acc.y += v.y; acc.z += v.z; acc.w += v.w;
    }
    float id = g_invdeg[w];
    acc.x *= id; acc.y *= id; acc.z *= id; acc.w *= id;
    __nv_bfloat162 hA = __floats2bfloat162_rn(acc.x, acc.y);
    __nv_bfloat162 hB = __floats2bfloat162_rn(acc.z, acc.w);
    __nv_bfloat162 lA = __floats2bfloat162_rn(acc.x - __low2float(hA), acc.y - __high2float(hA));
    __nv_bfloat162 lB = __floats2bfloat162_rn(acc.z - __low2float(hB), acc.w - __high2float(hB));
    uint2 ph, pl;
    ph.x = *(uint32_t*)&hA; ph.y = *(uint32_t*)&hB;
    pl.x = *(uint32_t*)&lA; pl.y = *(uint32_t*)&lB;
    *(uint2*)&g_aggh[w * HH + lane * 4] = ph;
    *(uint2*)&g_aggl[w * HH + lane * 4] = pl;
}

// ---------------- HMMA GEMM: zout = [agg|z] @ [Wl;Wr] + b  (K=256 pipelined) --
// 512 threads (16 warps: 4x4), warp tile 32x32, fp32 = hi+lo bf16 split.
// K streamed as 4 chunks of 64 with cp.async double buffering (2x64KB).
// chunk tile: 128 rows x 64 cols bf16 = 128B/row (8 x 16B), XOR swizzle.
#define CH_TILE 16384
#define OFF_AH  0
#define OFF_AL  32768
#define OFF_BH  65536
#define OFF_BL  98304
#define GEMM_SMEM 131072

__device__ __forceinline__ void cpa16(uint32_t dst, const void* src, uint32_t zf) {
    asm volatile("cp.async.cg.shared.global [%0], [%1], 16, %2;"
        :: "r"(dst), "l"(src), "r"(zf) : "memory");
}
__device__ __forceinline__ void cpa16u(uint32_t dst, const void* src) {
    asm volatile("cp.async.cg.shared.global [%0], [%1], 16;"
        :: "r"(dst), "l"(src) : "memory");
}

__device__ __forceinline__ void stage_chunk(uint32_t sb, int b,
        const __nv_bfloat16* ah, const __nv_bfloat16* al,
        const __nv_bfloat16* bh, const __nv_bfloat16* bl,
        int colofs, int row0, int t) {
    for (int i = t; i < 1024; i += 512) {
        int row = i >> 3, ch = i & 7;
        uint32_t sw = (uint32_t)(row * 128 + ((ch ^ (row & 7)) * 16));
        int gr = row0 + row;
        uint32_t zf = (gr < NN) ? 16u : 0u;
        size_t ao = (size_t)gr * HH + colofs + ch * 8;
        cpa16(sb + OFF_AH + b * CH_TILE + sw, ah + ao, zf);
        cpa16(sb + OFF_AL + b * CH_TILE + sw, al + ao, zf);
        size_t bo = (size_t)row * HH + colofs + ch * 8;
        cpa16u(sb + OFF_BH + b * CH_TILE + sw, bh + bo);
        cpa16u(sb + OFF_BL + b * CH_TILE + sw, bl + bo);
    }
    asm volatile("cp.async.commit_group;" ::: "memory");
}

__device__ __forceinline__ void compute_chunk(uint32_t sb, int b, int m0, int n0,
        int a_row, int a_chd, int b_row, int b_chd, float d[2][4][4]) {
    uint32_t aH = sb + OFF_AH + b * CH_TILE;
    uint32_t aL = sb + OFF_AL + b * CH_TILE;
    uint32_t bH = sb + OFF_BH + b * CH_TILE;
    uint32_t bL = sb + OFF_BL + b * CH_TILE;
#pragma unroll
    for (int ks = 0; ks < 4; ks++) {
        int c = ks * 2;
        uint32_t ah[2][4], al[2][4], bh[2][4], bl[2][4];
#pragma unroll
        for (int mt = 0; mt < 2; mt++) {
            int row = m0 + mt * 16 + a_row;
            int ch = c + a_chd;
            uint32_t o = (uint32_t)(row * 128 + ((ch ^ (row & 7)) * 16));
            ldsm4(ah[mt], aH + o);
            ldsm4(al[mt], aL + o);
        }
#pragma unroll
        for (int np = 0; np < 2; np++) {
            int row = n0 + np * 16 + b_row;
            int ch = c + b_chd;
            uint32_t o = (uint32_t)(row * 128 + ((ch ^ (row & 7)) * 16));
            ldsm4(bh[np], bH + o);
            ldsm4(bl[np], bL + o);
        }
#pragma unroll
        for (int mt = 0; mt < 2; mt++)
#pragma unroll
            for (int nt = 0; nt < 4; nt++) {
                const uint32_t* fh = &bh[nt >> 1][(nt & 1) * 2];
                const uint32_t* fl = &bl[nt >> 1][(nt & 1) * 2];
                mma16816(d[mt][nt], ah[mt], fh);   // hi*hi
                mma16816(d[mt][nt], ah[mt], fl);   // hi*lo
                mma16816(d[mt][nt], al[mt], fh);   // lo*hi
            }
    }
}

__global__ void __launch_bounds__(512, 1)
k_gemm_mma(const __nv_bfloat16* __restrict__ wlh, const __nv_bfloat16* __restrict__ wll,
           const __nv_bfloat16* __restrict__ wrh, const __nv_bfloat16* __restrict__ wrl,
           const float* __restrict__ bias, float* __restrict__ zout) {
    extern __shared__ char smb[];
    uint32_t sb = smem_u32(smb);
    const int t = threadIdx.x, wid = t >> 5, lane = t & 31;
    const int m0 = (wid & 3) * 32;       // 4 m-groups x 32 rows
    const int n0 = (wid >> 2) * 32;      // 4 n-groups x 32 cols
    const int row0 = blockIdx.x * MT;
    const int g = lane >> 2, tid4 = lane & 3;

    const int a_row = lane & 15, a_chd = lane >> 4;
    const int b_row = (lane & 7) + ((lane >> 4) << 3), b_chd = (lane >> 3) & 1;

    float d[2][4][4];
#pragma unroll
    for (int mt = 0; mt < 2; mt++)
#pragma unroll
        for (int nt = 0; nt < 4; nt++)
#pragma unroll
            for (int j = 0; j < 4; j++) d[mt][nt][j] = 0.f;

    // chunk c: A = (c<2 ? agg : z) cols (c&1)*64,  B = (c<2 ? Wl : Wr) same cols
    const __nv_bfloat16* Ah[4] = {g_aggh, g_aggh, g_zh, g_zh};
    const __nv_bfloat16* Al[4] = {g_aggl, g_aggl, g_zl, g_zl};
    const __nv_bfloat16* Bh[4] = {wlh, wlh, wrh, wrh};
    const __nv_bfloat16* Bl[4] = {wll, wll, wrl, wrl};

    stage_chunk(sb, 0, Ah[0], Al[0], Bh[0], Bl[0], 0, row0, t);
#pragma unroll
    for (int c = 0; c < 4; c++) {
        if (c + 1 < 4) {
            stage_chunk(sb, (c + 1) & 1, Ah[c + 1], Al[c + 1], Bh[c + 1], Bl[c + 1],
                        ((c + 1) & 1) * 64, row0, t);
            asm volatile("cp.async.wait_group 1;" ::: "memory");
        } else {
            asm volatile("cp.async.wait_group 0;" ::: "memory");
        }
        __syncthreads();
        compute_chunk(sb, c & 1, m0, n0, a_row, a_chd, b_row, b_chd, d);
        __syncthreads();
    }

    // epilogue: D fragment (16x8): d0=(g, tid4*2) d1=+1 d2=(g+8,..) d3
#pragma unroll
    for (int mt = 0; mt < 2; mt++) {
        int r_up = row0 + m0 + mt * 16 + g;
        int r_dn = r_up + 8;
#pragma unroll
        for (int nt = 0; nt < 4; nt++) {
            int cc = n0 + nt * 8 + tid4 * 2;
            float b0 = bias[cc], b1 = bias[cc + 1];
            if (r_up < NN) {
                float2 o = make_float2(d[mt][nt][0] + b0, d[mt][nt][1] + b1);
                *(float2*)&zout[(size_t)r_up * HH + cc] = o;
            }
            if (r_dn < NN) {
                float2 o = make_float2(d[mt][nt][2] + b0, d[mt][nt][3] + b1);
                *(float2*)&zout[(size_t)r_dn * HH + cc] = o;
            }
        }
    }
}

// ---------------- BatchNorm ----------------
__global__ void k_bnstats(const float* __restrict__ z) {
    int h = threadIdx.x;
    int r0 = blockIdx.x * 256;
    int rend = r0 + 256; if (rend > NN) rend = NN;
    float s = 0.f, ss = 0.f;
    for (int r = r0; r < rend; r++) {
        float v = z[r * HH + h];
        s += v; ss = fmaf(v, v, ss);
    }
    atomicAdd(&g_bnsum[h], s);
    atomicAdd(&g_bnsq[h], ss);
}
__global__ void k_bnfin(const float* __restrict__ gamma, const float* __restrict__ beta) {
    int h = threadIdx.x;
    float inv = 1.0f / (float)NN;
    float mu = g_bnsum[h] * inv;
    float var = g_bnsq[h] * inv - mu * mu;
    float sc = gamma[h] * rsqrtf(var + 1e-5f);
    g_scale[h] = sc;
    g_shift[h] = beta[h] - mu * sc;
}
// BN + ReLU in place, also emit bf16 hi/lo of the result
__global__ void k_bnapply(float* __restrict__ z) {
    int i = blockIdx.x * blockDim.x + threadIdx.x;
    if (i >= NN * (HH / 4)) return;
    int h4 = i & 31;
    float4 v = ((float4*)z)[i];
    float4 sc = ((const float4*)g_scale)[h4];
    float4 sh = ((const float4*)g_shift)[h4];
    v.x = fmaxf(fmaf(v.x, sc.x, sh.x), 0.f);
    v.y = fmaxf(fmaf(v.y, sc.y, sh.y), 0.f);
    v.z = fmaxf(fmaf(v.z, sc.z, sh.z), 0.f);
    v.w = fmaxf(fmaf(v.w, sc.w, sh.w), 0.f);
    ((float4*)z)[i] = v;
    __nv_bfloat162 hA = __floats2bfloat162_rn(v.x, v.y);
    __nv_bfloat162 hB = __floats2bfloat162_rn(v.z, v.w);
    __nv_bfloat162 lA = __floats2bfloat162_rn(v.x - __low2float(hA), v.y - __high2float(hA));
    __nv_bfloat162 lB = __floats2bfloat162_rn(v.z - __low2float(hB), v.w - __high2float(hB));
    uint2 ph, pl;
    ph.x = *(uint32_t*)&hA; ph.y = *(uint32_t*)&hB;
    pl.x = *(uint32_t*)&lA; pl.y = *(uint32_t*)&lB;
    *(uint2*)&g_zh[i * 4] = ph;
    *(uint2*)&g_zl[i * 4] = pl;
}

// ---------------- decoder ----------------
__global__ void k_dec(const float* __restrict__ z, const float* __restrict__ dW,
                      const float* __restrict__ db, float* __restrict__ out) {
    __shared__ float W[HH * OUTF];
    for (int i = threadIdx.x; i < HH * OUTF; i += blockDim.x) W[i] = dW[i];
    __syncthreads();
    int w = (blockIdx.x * blockDim.x + threadIdx.x) >> 5;
    int lane = threadIdx.x & 31;
    if (w >= NN) return;
    float4 zv = *(const float4*)&z[w * HH + lane * 4];
    int h = lane * 4;
    float o0 = zv.x * W[h * 4 + 0] + zv.y * W[(h + 1) * 4 + 0] + zv.z * W[(h + 2) * 4 + 0] + zv.w * W[(h + 3) * 4 + 0];
    float o1 = zv.x * W[h * 4 + 1] + zv.y * W[(h + 1) * 4 + 1] + zv.z * W[(h + 2) * 4 + 1] + zv.w * W[(h + 3) * 4 + 1];
    float o2 = zv.x * W[h * 4 + 2] + zv.y * W[(h + 1) * 4 + 2] + zv.z * W[(h + 2) * 4 + 2] + zv.w * W[(h + 3) * 4 + 2];
    float o3 = zv.x * W[h * 4 + 3] + zv.y * W[(h + 1) * 4 + 3] + zv.z * W[(h + 2) * 4 + 3] + zv.w * W[(h + 3) * 4 + 3];
#pragma unroll
    for (int d = 16; d; d >>= 1) {
        o0 += __shfl_down_sync(0xFFFFFFFFu, o0, d);
        o1 += __shfl_down_sync(0xFFFFFFFFu, o1, d);
        o2 += __shfl_down_sync(0xFFFFFFFFu, o2, d);
        o3 += __shfl_down_sync(0xFFFFFFFFu, o3, d);
    }
    if (lane == 0) {
        float4 r;
        r.x = o0 + db[0]; r.y = o1 + db[1]; r.z = o2 + db[2]; r.w = o3 + db[3];
        *(float4*)&out[w * 4] = r;
    }
}

// ---------------- launch ----------------
extern "C" void kernel_launch(void* const* d_in, const int* in_sizes, int n_in,
                              void* d_out, int out_size) {
    const float* x      = (const float*)d_in[0];
    const float* enc_W  = (const float*)d_in[1];
    const float* enc_b  = (const float*)d_in[2];
    const float* Wl     = (const float*)d_in[3];
    const float* Wr     = (const float*)d_in[4];
    const float* b      = (const float*)d_in[5];
    const float* bng    = (const float*)d_in[6];
    const float* bnb    = (const float*)d_in[7];
    const float* dec_W  = (const float*)d_in[8];
    const float* dec_b  = (const float*)d_in[9];
    const void*  ei     = d_in[10];
    float* out = (float*)d_out;

    float *zA, *zB;
    __nv_bfloat16 *Wth, *Wtl;
    void* p;
    cudaGetSymbolAddress(&p, g_zA);  zA  = (float*)p;
    cudaGetSymbolAddress(&p, g_zB);  zB  = (float*)p;
    cudaGetSymbolAddress(&p, g_Wth); Wth = (__nv_bfloat16*)p;
    cudaGetSymbolAddress(&p, g_Wtl); Wtl = (__nv_bfloat16*)p;
    void *pdeg, *pbnsum, *pbnsq;
    cudaGetSymbolAddress(&pdeg, g_deg);
    cudaGetSymbolAddress(&pbnsum, g_bnsum);
    cudaGetSymbolAddress(&pbnsq, g_bnsq);

    cudaFuncSetAttribute(k_gemm_mma, cudaFuncAttributeMaxDynamicSharedMemorySize, GEMM_SMEM);

    const int TB = 256;
    const int egrid = (EE + TB - 1) / TB;

    // CSR build + W conversion
    k_detect<<<1, 32>>>((const int*)ei);
    cudaMemsetAsync(pdeg, 0, NN * sizeof(int));
    k_degree<<<egrid, TB>>>(ei);
    k_scan1<<<(NN + 1023) / 1024, 1024>>>();
    k_scan2<<<1, 32>>>((NN + 1023) / 1024);
    k_scan3<<<(NN + TB - 1) / TB, TB>>>();
    k_scatter<<<egrid, TB>>>(ei);
    k_wconv<<<(2 * NL * HH * HH + TB - 1) / TB, TB>>>(Wl, Wr);

    k_enc<<<(NN * HH + TB - 1) / TB, TB>>>(x, enc_W, enc_b, zA);

    float* zin = zA;
    float* zout = zB;
    for (int i = 0; i < NL; i++) {
        k_agg<<<(NN * 32 + TB - 1) / TB, TB>>>(zin);
        k_gemm_mma<<<NTILES, 512, GEMM_SMEM>>>(
            Wth + (size_t)(2 * i + 0) * HH * HH, Wtl + (size_t)(2 * i + 0) * HH * HH,
            Wth + (size_t)(2 * i + 1) * HH * HH, Wtl + (size_t)(2 * i + 1) * HH * HH,
            b + (size_t)i * HH, zout);
        if (i < NL - 1) {
            cudaMemsetAsync(pbnsum, 0, HH * sizeof(float));
            cudaMemsetAsync(pbnsq, 0, HH * sizeof(float));
            k_bnstats<<<(NN + 255) / 256, HH>>>(zout);
            k_bnfin<<<1, HH>>>(bng + (size_t)i * HH, bnb + (size_t)i * HH);
            k_bnapply<<<(NN * (HH / 4) + TB - 1) / TB, TB>>>(zout);
        }
        float* tmp = zin; zin = zout; zout = tmp;
    }

    k_dec<<<(NN * 32 + TB - 1) / TB, TB>>>(zin, dec_W, dec_b, out);
}

// round 10
// speedup vs baseline: 1.6574x; 1.0044x over previous
#include <cuda_runtime.h>
#include <cuda_bf16.h>
#include <math.h>
#include <stdint.h>

#define NN   50000
#define EE   600000
#define HH   128
#define INF  7
#define OUTF 4
#define NL   4
#define MT   128
#define NTILES ((NN + MT - 1) / MT)

// ---------------- scratch ----------------
__device__ float g_zA[NN * HH];
__device__ float g_zB[NN * HH];
__device__ __nv_bfloat16 g_aggh[NN * HH];
__device__ __nv_bfloat16 g_aggl[NN * HH];
__device__ __nv_bfloat16 g_zh[NN * HH];
__device__ __nv_bfloat16 g_zl[NN * HH];
__device__ __nv_bfloat16 g_Wth[2 * NL * HH * HH];   // [layer*2+which][n][k] (transposed)
__device__ __nv_bfloat16 g_Wtl[2 * NL * HH * HH];
__device__ int   g_deg[NN];
__device__ int   g_scan[NN];
__device__ int   g_rowptr[NN + 1];
__device__ int   g_fill[NN];
__device__ int   g_col[EE];
__device__ float g_invdeg[NN];
__device__ int   g_bsum[64];
__device__ int   g_boff[64];
__device__ float g_bnsum[HH];
__device__ float g_bnsq[HH];
__device__ float g_scale[HH];
__device__ float g_shift[HH];
__device__ int   g_is64;

__device__ __forceinline__ uint32_t smem_u32(const void* p) {
    uint32_t a;
    asm("{ .reg .u64 t; cvta.to.shared.u64 t, %1; cvt.u32.u64 %0, t; }" : "=r"(a) : "l"(p));
    return a;
}

// ---------------- warp-level tensor ops (baseline PTX, sm_80+) ----------------
__device__ __forceinline__ void ldsm4(uint32_t* r, uint32_t addr) {
    asm volatile("ldmatrix.sync.aligned.m8n8.x4.shared.b16 {%0,%1,%2,%3}, [%4];"
        : "=r"(r[0]), "=r"(r[1]), "=r"(r[2]), "=r"(r[3]) : "r"(addr));
}
__device__ __forceinline__ void mma16816(float* d, const uint32_t* a, const uint32_t* b) {
    asm volatile("mma.sync.aligned.m16n8k16.row.col.f32.bf16.bf16.f32 "
        "{%0,%1,%2,%3}, {%4,%5,%6,%7}, {%8,%9}, {%0,%1,%2,%3};"
        : "+f"(d[0]), "+f"(d[1]), "+f"(d[2]), "+f"(d[3])
        : "r"(a[0]), "r"(a[1]), "r"(a[2]), "r"(a[3]), "r"(b[0]), "r"(b[1]));
}

// ---------------- edge-index dtype probe ----------------
__global__ void k_detect(const int* __restrict__ ei32) {
    if (threadIdx.x == 0) {
        int z = 0;
#pragma unroll
        for (int i = 0; i < 16; i++) z |= ei32[2 * i + 1];
        g_is64 = (z == 0) ? 1 : 0;
    }
}
__device__ __forceinline__ int clampN(int v) {
    v = v < 0 ? 0 : v;
    return v >= NN ? NN - 1 : v;
}
__device__ __forceinline__ int edge_src(const void* ei, int e) {
    int v = g_is64 ? (int)((const long long*)ei)[e] : ((const int*)ei)[e];
    return clampN(v);
}
__device__ __forceinline__ int edge_dst(const void* ei, int e) {
    int v = g_is64 ? (int)((const long long*)ei)[EE + e] : ((const int*)ei)[EE + e];
    return clampN(v);
}

// ---------------- CSR build ----------------
__global__ void k_degree(const void* __restrict__ ei) {
    int e = blockIdx.x * blockDim.x + threadIdx.x;
    if (e < EE) atomicAdd(&g_deg[edge_dst(ei, e)], 1);
}
__global__ void k_scan1() {
    __shared__ int wsum[32];
    int i = blockIdx.x * 1024 + threadIdx.x;
    int v = (i < NN) ? g_deg[i] : 0;
    int lane = threadIdx.x & 31, wid = threadIdx.x >> 5;
    int x = v;
#pragma unroll
    for (int d = 1; d < 32; d <<= 1) {
        int y = __shfl_up_sync(0xFFFFFFFFu, x, d);
        if (lane >= d) x += y;
    }
    if (lane == 31) wsum[wid] = x;
    __syncthreads();
    if (wid == 0) {
        int s = wsum[lane];
#pragma unroll
        for (int d = 1; d < 32; d <<= 1) {
            int y = __shfl_up_sync(0xFFFFFFFFu, s, d);
            if (lane >= d) s += y;
        }
        wsum[lane] = s;
    }
    __syncthreads();
    int off = (wid > 0) ? wsum[wid - 1] : 0;
    int incl = x + off;
    if (i < NN) g_scan[i] = incl;
    if (threadIdx.x == 1023) g_bsum[blockIdx.x] = incl;
}
__global__ void k_scan2(int nblk) {
    int lane = threadIdx.x & 31;
    int i0 = 2 * lane, i1 = 2 * lane + 1;
    int a = (i0 < nblk) ? g_bsum[i0] : 0;
    int b = (i1 < nblk) ? g_bsum[i1] : 0;
    int s = a + b;
    int x = s;
#pragma unroll
    for (int d = 1; d < 32; d <<= 1) {
        int y = __shfl_up_sync(0xFFFFFFFFu, x, d);
        if (lane >= d) x += y;
    }
    int excl = x - s;
    if (i0 < nblk) g_boff[i0] = excl;
    if (i1 < nblk) g_boff[i1] = excl + a;
}
__global__ void k_scan3() {
    int i = blockIdx.x * blockDim.x + threadIdx.x;
    if (i < NN) {
        g_rowptr[i + 1] = g_scan[i] + g_boff[i >> 10];
        if (i == 0) g_rowptr[0] = 0;
        g_fill[i] = 0;
        int d = g_deg[i];
        g_invdeg[i] = 1.0f / (float)(d > 1 ? d : 1);
    }
}
__global__ void k_scatter(const void* __restrict__ ei) {
    int e = blockIdx.x * blockDim.x + threadIdx.x;
    if (e < EE) {
        int dst = edge_dst(ei, e);
        int src = edge_src(ei, e);
        int p = g_rowptr[dst] + atomicAdd(&g_fill[dst], 1);
        g_col[p] = src;
    }
}

// ---------------- W transpose + bf16 split (once per launch) ----------------
__global__ void k_wconv(const float* __restrict__ Wl, const float* __restrict__ Wr) {
    int idx = blockIdx.x * blockDim.x + threadIdx.x;
    if (idx >= 2 * NL * HH * HH) return;
    int m2 = idx / (HH * HH);
    int rem = idx - m2 * (HH * HH);
    int n = rem >> 7, k = rem & 127;
    int layer = m2 >> 1;
    const float* src = (m2 & 1) ? Wr : Wl;
    float v = src[layer * HH * HH + k * HH + n];      // B[n][k] = W[k][n]
    __nv_bfloat16 hi = __float2bfloat16_rn(v);
    __nv_bfloat16 lo = __float2bfloat16_rn(v - __bfloat162float(hi));
    g_Wth[m2 * HH * HH + n * HH + k] = hi;
    g_Wtl[m2 * HH * HH + n * HH + k] = lo;
}

// ---------------- encoder (emits fp32 z + bf16 hi/lo) ----------------
__global__ void k_enc(const float* __restrict__ x, const float* __restrict__ eW,
                      const float* __restrict__ eb, float* __restrict__ z) {
    __shared__ float W[INF * HH];
    for (int i = threadIdx.x; i < INF * HH; i += blockDim.x) W[i] = eW[i];
    __syncthreads();
    int idx = blockIdx.x * blockDim.x + threadIdx.x;
    if (idx >= NN * HH) return;
    int n = idx >> 7, h = idx & 127;
    float s = eb[h];
    const float* xr = x + n * INF;
#pragma unroll
    for (int k = 0; k < INF; k++) s = fmaf(xr[k], W[k * HH + h], s);
    z[idx] = s;
    __nv_bfloat16 hi = __float2bfloat16_rn(s);
    g_zh[idx] = hi;
    g_zl[idx] = __float2bfloat16_rn(s - __bfloat162float(hi));
}

// ---------------- aggregation (+optional fused BN/ReLU of zin), emits bf16 agg
__global__ void k_agg(const float* __restrict__ zin, int apply_bn) {
    int w = (blockIdx.x * blockDim.x + threadIdx.x) >> 5;
    int lane = threadIdx.x & 31;
    if (w >= NN) return;
    float4 sc = make_float4(1.f, 1.f, 1.f, 1.f);
    float4 sh = make_float4(0.f, 0.f, 0.f, 0.f);
    if (apply_bn) {
        sc = ((const float4*)g_scale)[lane];
        sh = ((const float4*)g_shift)[lane];
    }
    int beg = g_rowptr[w], end = g_rowptr[w + 1];
    float4 acc = make_float4(0.f, 0.f, 0.f, 0.f);
    for (int j = beg; j < end; j++) {
        int s = g_col[j];
        float4 v = *(const float4*)&zin[s * HH + lane * 4];
        if (apply_bn) {
            v.x = fmaxf(fmaf(v.x, sc.x, sh.x), 0.f);
            v.y = fmaxf(fmaf(v.y, sc.y, sh.y), 0.f);
            v.z = fmaxf(fmaf(v.z, sc.z, sh.z), 0.f);
            v.w = fmaxf(fmaf(v.w, sc.w, sh.w), 0.f);
        }
        acc.x += v.x; acc.y += v.y; acc.z += v.z; acc.w += v.w;
    }
    float id = g_invdeg[w];
    acc.x *= id; acc.y *= id; acc.z *= id; acc.w *= id;
    __nv_bfloat162 hA = __floats2bfloat162_rn(acc.x, acc.y);
    __nv_bfloat162 hB = __floats2bfloat162_rn(acc.z, acc.w);
    __nv_bfloat162 lA = __floats2bfloat162_rn(acc.x - __low2float(hA), acc.y - __high2float(hA));
    __nv_bfloat162 lB = __floats2bfloat162_rn(acc.z - __low2float(hB), acc.w - __high2float(hB));
    uint2 ph, pl;
    ph.x = *(uint32_t*)&hA; ph.y = *(uint32_t*)&hB;
    pl.x = *(uint32_t*)&lA; pl.y = *(uint32_t*)&lB;
    *(uint2*)&g_aggh[w * HH + lane * 4] = ph;
    *(uint2*)&g_aggl[w * HH + lane * 4] = pl;
}

// ---------------- HMMA GEMM: zout = [agg|z] @ [Wl;Wr] + b  (K=256 pipelined) --
// 512 threads (16 warps: 4x4), warp tile 32x32, fp32 = hi+lo bf16 split.
// K streamed as 4 chunks of 64 with cp.async double buffering.
// Fused BN stats: per-column sum/sumsq reduced in-epilogue -> global atomics.
#define CH_TILE 16384
#define OFF_AH  0
#define OFF_AL  32768
#define OFF_BH  65536
#define OFF_BL  98304
#define GEMM_SMEM 131072

__device__ __forceinline__ void cpa16(uint32_t dst, const void* src, uint32_t zf) {
    asm volatile("cp.async.cg.shared.global [%0], [%1], 16, %2;"
        :: "r"(dst), "l"(src), "r"(zf) : "memory");
}
__device__ __forceinline__ void cpa16u(uint32_t dst, const void* src) {
    asm volatile("cp.async.cg.shared.global [%0], [%1], 16;"
        :: "r"(dst), "l"(src) : "memory");
}

__device__ __forceinline__ void stage_chunk(uint32_t sb, int b,
        const __nv_bfloat16* ah, const __nv_bfloat16* al,
        const __nv_bfloat16* bh, const __nv_bfloat16* bl,
        int colofs, int row0, int t) {
    for (int i = t; i < 1024; i += 512) {
        int row = i >> 3, ch = i & 7;
        uint32_t sw = (uint32_t)(row * 128 + ((ch ^ (row & 7)) * 16));
        int gr = row0 + row;
        uint32_t zf = (gr < NN) ? 16u : 0u;
        size_t ao = (size_t)gr * HH + colofs + ch * 8;
        cpa16(sb + OFF_AH + b * CH_TILE + sw, ah + ao, zf);
        cpa16(sb + OFF_AL + b * CH_TILE + sw, al + ao, zf);
        size_t bo = (size_t)row * HH + colofs + ch * 8;
        cpa16u(sb + OFF_BH + b * CH_TILE + sw, bh + bo);
        cpa16u(sb + OFF_BL + b * CH_TILE + sw, bl + bo);
    }
    asm volatile("cp.async.commit_group;" ::: "memory");
}

__device__ __forceinline__ void compute_chunk(uint32_t sb, int b, int m0, int n0,
        int a_row, int a_chd, int b_row, int b_chd, float d[2][4][4]) {
    uint32_t aH = sb + OFF_AH + b * CH_TILE;
    uint32_t aL = sb + OFF_AL + b * CH_TILE;
    uint32_t bH = sb + OFF_BH + b * CH_TILE;
    uint32_t bL = sb + OFF_BL + b * CH_TILE;
#pragma unroll
    for (int ks = 0; ks < 4; ks++) {
        int c = ks * 2;
        uint32_t ah[2][4], al[2][4], bh[2][4], bl[2][4];
#pragma unroll
        for (int mt = 0; mt < 2; mt++) {
            int row = m0 + mt * 16 + a_row;
            int ch = c + a_chd;
            uint32_t o = (uint32_t)(row * 128 + ((ch ^ (row & 7)) * 16));
            ldsm4(ah[mt], aH + o);
            ldsm4(al[mt], aL + o);
        }
#pragma unroll
        for (int np = 0; np < 2; np++) {
            int row = n0 + np * 16 + b_row;
            int ch = c + b_chd;
            uint32_t o = (uint32_t)(row * 128 + ((ch ^ (row & 7)) * 16));
            ldsm4(bh[np], bH + o);
            ldsm4(bl[np], bL + o);
        }
#pragma unroll
        for (int mt = 0; mt < 2; mt++)
#pragma unroll
            for (int nt = 0; nt < 4; nt++) {
                const uint32_t* fh = &bh[nt >> 1][(nt & 1) * 2];
                const uint32_t* fl = &bl[nt >> 1][(nt & 1) * 2];
                mma16816(d[mt][nt], ah[mt], fh);   // hi*hi
                mma16816(d[mt][nt], ah[mt], fl);   // hi*lo
                mma16816(d[mt][nt], al[mt], fh);   // lo*hi
            }
    }
}

__global__ void __launch_bounds__(512, 1)
k_gemm_mma(const __nv_bfloat16* __restrict__ wlh, const __nv_bfloat16* __restrict__ wll,
           const __nv_bfloat16* __restrict__ wrh, const __nv_bfloat16* __restrict__ wrl,
           const float* __restrict__ bias, float* __restrict__ zout, int do_stats) {
    extern __shared__ char smb[];
    uint32_t sb = smem_u32(smb);
    const int t = threadIdx.x, wid = t >> 5, lane = t & 31;
    const int m0 = (wid & 3) * 32;
    const int n0 = (wid >> 2) * 32;
    const int row0 = blockIdx.x * MT;
    const int g = lane >> 2, tid4 = lane & 3;

    const int a_row = lane & 15, a_chd = lane >> 4;
    const int b_row = (lane & 7) + ((lane >> 4) << 3), b_chd = (lane >> 3) & 1;

    float d[2][4][4];
#pragma unroll
    for (int mt = 0; mt < 2; mt++)
#pragma unroll
        for (int nt = 0; nt < 4; nt++)
#pragma unroll
            for (int j = 0; j < 4; j++) d[mt][nt][j] = 0.f;

    const __nv_bfloat16* Ah[4] = {g_aggh, g_aggh, g_zh, g_zh};
    const __nv_bfloat16* Al[4] = {g_aggl, g_aggl, g_zl, g_zl};
    const __nv_bfloat16* Bh[4] = {wlh, wlh, wrh, wrh};
    const __nv_bfloat16* Bl[4] = {wll, wll, wrl, wrl};

    stage_chunk(sb, 0, Ah[0], Al[0], Bh[0], Bl[0], 0, row0, t);
#pragma unroll
    for (int c = 0; c < 4; c++) {
        if (c + 1 < 4) {
            stage_chunk(sb, (c + 1) & 1, Ah[c + 1], Al[c + 1], Bh[c + 1], Bl[c + 1],
                        ((c + 1) & 1) * 64, row0, t);
            asm volatile("cp.async.wait_group 1;" ::: "memory");
        } else {
            asm volatile("cp.async.wait_group 0;" ::: "memory");
        }
        __syncthreads();
        compute_chunk(sb, c & 1, m0, n0, a_row, a_chd, b_row, b_chd, d);
        __syncthreads();
    }

    // smem reuse for BN stats
    float* ssum = (float*)smb;
    float* ssq  = ssum + HH;
    if (do_stats && t < 2 * HH) ssum[t] = 0.f;
    __syncthreads();

    float s_acc[4][2], q_acc[4][2];
#pragma unroll
    for (int nt = 0; nt < 4; nt++) { s_acc[nt][0] = s_acc[nt][1] = 0.f; q_acc[nt][0] = q_acc[nt][1] = 0.f; }

#pragma unroll
    for (int mt = 0; mt < 2; mt++) {
        int r_up = row0 + m0 + mt * 16 + g;
        int r_dn = r_up + 8;
#pragma unroll
        for (int nt = 0; nt < 4; nt++) {
            int cc = n0 + nt * 8 + tid4 * 2;
            float b0 = bias[cc], b1 = bias[cc + 1];
            if (r_up < NN) {
                float v0 = d[mt][nt][0] + b0, v1 = d[mt][nt][1] + b1;
                *(float2*)&zout[(size_t)r_up * HH + cc] = make_float2(v0, v1);
                s_acc[nt][0] += v0; q_acc[nt][0] = fmaf(v0, v0, q_acc[nt][0]);
                s_acc[nt][1] += v1; q_acc[nt][1] = fmaf(v1, v1, q_acc[nt][1]);
            }
            if (r_dn < NN) {
                float v2 = d[mt][nt][2] + b0, v3 = d[mt][nt][3] + b1;
                *(float2*)&zout[(size_t)r_dn * HH + cc] = make_float2(v2, v3);
                s_acc[nt][0] += v2; q_acc[nt][0] = fmaf(v2, v2, q_acc[nt][0]);
                s_acc[nt][1] += v3; q_acc[nt][1] = fmaf(v3, v3, q_acc[nt][1]);
            }
        }
    }

    if (do_stats) {
#pragma unroll
        for (int nt = 0; nt < 4; nt++)
#pragma unroll
            for (int j = 0; j < 2; j++) {
                float sv = s_acc[nt][j], qv = q_acc[nt][j];
                sv += __shfl_down_sync(0xFFFFFFFFu, sv, 16);
                qv += __shfl_down_sync(0xFFFFFFFFu, qv, 16);
                sv += __shfl_down_sync(0xFFFFFFFFu, sv, 8);
                qv += __shfl_down_sync(0xFFFFFFFFu, qv, 8);
                sv += __shfl_down_sync(0xFFFFFFFFu, sv, 4);
                qv += __shfl_down_sync(0xFFFFFFFFu, qv, 4);
                if (g == 0) {
                    int cc = n0 + nt * 8 + tid4 * 2 + j;
                    atomicAdd(&ssum[cc], sv);
                    atomicAdd(&ssq[cc], qv);
                }
            }
        __syncthreads();
        if (t < HH) {
            atomicAdd(&g_bnsum[t], ssum[t]);
            atomicAdd(&g_bnsq[t], ssq[t]);
        }
    }
}

// ---------------- BatchNorm finalize + bf16 split of BN'd z -----------------
__global__ void k_bnfin(const float* __restrict__ gamma, const float* __restrict__ beta) {
    int h = threadIdx.x;
    float inv = 1.0f / (float)NN;
    float mu = g_bnsum[h] * inv;
    float var = g_bnsq[h] * inv - mu * mu;
    float sc = gamma[h] * rsqrtf(var + 1e-5f);
    g_scale[h] = sc;
    g_shift[h] = beta[h] - mu * sc;
}
// reads raw z, writes bf16 hi/lo of BN+ReLU(z). fp32 z stays raw (agg applies BN on the fly).
__global__ void k_bnapply(const float* __restrict__ z) {
    int i = blockIdx.x * blockDim.x + threadIdx.x;
    if (i >= NN * (HH / 4)) return;
    int h4 = i & 31;
    float4 v = ((const float4*)z)[i];
    float4 sc = ((const float4*)g_scale)[h4];
    float4 sh = ((const float4*)g_shift)[h4];
    v.x = fmaxf(fmaf(v.x, sc.x, sh.x), 0.f);
    v.y = fmaxf(fmaf(v.y, sc.y, sh.y), 0.f);
    v.z = fmaxf(fmaf(v.z, sc.z, sh.z), 0.f);
    v.w = fmaxf(fmaf(v.w, sc.w, sh.w), 0.f);
    __nv_bfloat162 hA = __floats2bfloat162_rn(v.x, v.y);
    __nv_bfloat162 hB = __floats2bfloat162_rn(v.z, v.w);
    __nv_bfloat162 lA = __floats2bfloat162_rn(v.x - __low2float(hA), v.y - __high2float(hA));
    __nv_bfloat162 lB = __floats2bfloat162_rn(v.z - __low2float(hB), v.w - __high2float(hB));
    uint2 ph, pl;
    ph.x = *(uint32_t*)&hA; ph.y = *(uint32_t*)&hB;
    pl.x = *(uint32_t*)&lA; pl.y = *(uint32_t*)&lB;
    *(uint2*)&g_zh[i * 4] = ph;
    *(uint2*)&g_zl[i * 4] = pl;
}

// ---------------- decoder ----------------
__global__ void k_dec(const float* __restrict__ z, const float* __restrict__ dW,
                      const float* __restrict__ db, float* __restrict__ out) {
    __shared__ float W[HH * OUTF];
    for (int i = threadIdx.x; i < HH * OUTF; i += blockDim.x) W[i] = dW[i];
    __syncthreads();
    int w = (blockIdx.x * blockDim.x + threadIdx.x) >> 5;
    int lane = threadIdx.x & 31;
    if (w >= NN) return;
    float4 zv = *(const float4*)&z[w * HH + lane * 4];
    int h = lane * 4;
    float o0 = zv.x * W[h * 4 + 0] + zv.y * W[(h + 1) * 4 + 0] + zv.z * W[(h + 2) * 4 + 0] + zv.w * W[(h + 3) * 4 + 0];
    float o1 = zv.x * W[h * 4 + 1] + zv.y * W[(h + 1) * 4 + 1] + zv.z * W[(h + 2) * 4 + 1] + zv.w * W[(h + 3) * 4 + 1];
    float o2 = zv.x * W[h * 4 + 2] + zv.y * W[(h + 1) * 4 + 2] + zv.z * W[(h + 2) * 4 + 2] + zv.w * W[(h + 3) * 4 + 2];
    float o3 = zv.x * W[h * 4 + 3] + zv.y * W[(h + 1) * 4 + 3] + zv.z * W[(h + 2) * 4 + 3] + zv.w * W[(h + 3) * 4 + 3];
#pragma unroll
    for (int d = 16; d; d >>= 1) {
        o0 += __shfl_down_sync(0xFFFFFFFFu, o0, d);
        o1 += __shfl_down_sync(0xFFFFFFFFu, o1, d);
        o2 += __shfl_down_sync(0xFFFFFFFFu, o2, d);
        o3 += __shfl_down_sync(0xFFFFFFFFu, o3, d);
    }
    if (lane == 0) {
        float4 r;
        r.x = o0 + db[0]; r.y = o1 + db[1]; r.z = o2 + db[2]; r.w = o3 + db[3];
        *(float4*)&out[w * 4] = r;
    }
}

// ---------------- launch ----------------
extern "C" void kernel_launch(void* const* d_in, const int* in_sizes, int n_in,
                              void* d_out, int out_size) {
    const float* x      = (const float*)d_in[0];
    const float* enc_W  = (const float*)d_in[1];
    const float* enc_b  = (const float*)d_in[2];
    const float* Wl     = (const float*)d_in[3];
    const float* Wr     = (const float*)d_in[4];
    const float* b      = (const float*)d_in[5];
    const float* bng    = (const float*)d_in[6];
    const float* bnb    = (const float*)d_in[7];
    const float* dec_W  = (const float*)d_in[8];
    const float* dec_b  = (const float*)d_in[9];
    const void*  ei     = d_in[10];
    float* out = (float*)d_out;

    float *zA, *zB;
    __nv_bfloat16 *Wth, *Wtl;
    void* p;
    cudaGetSymbolAddress(&p, g_zA);  zA  = (float*)p;
    cudaGetSymbolAddress(&p, g_zB);  zB  = (float*)p;
    cudaGetSymbolAddress(&p, g_Wth); Wth = (__nv_bfloat16*)p;
    cudaGetSymbolAddress(&p, g_Wtl); Wtl = (__nv_bfloat16*)p;
    void *pdeg, *pbnsum, *pbnsq;
    cudaGetSymbolAddress(&pdeg, g_deg);
    cudaGetSymbolAddress(&pbnsum, g_bnsum);
    cudaGetSymbolAddress(&pbnsq, g_bnsq);

    cudaFuncSetAttribute(k_gemm_mma, cudaFuncAttributeMaxDynamicSharedMemorySize, GEMM_SMEM);

    const int TB = 256;
    const int egrid = (EE + TB - 1) / TB;

    // CSR build + W conversion
    k_detect<<<1, 32>>>((const int*)ei);
    cudaMemsetAsync(pdeg, 0, NN * sizeof(int));
    k_degree<<<egrid, TB>>>(ei);
    k_scan1<<<(NN + 1023) / 1024, 1024>>>();
    k_scan2<<<1, 32>>>((NN + 1023) / 1024);
    k_scan3<<<(NN + TB - 1) / TB, TB>>>();
    k_scatter<<<egrid, TB>>>(ei);
    k_wconv<<<(2 * NL * HH * HH + TB - 1) / TB, TB>>>(Wl, Wr);

    k_enc<<<(NN * HH + TB - 1) / TB, TB>>>(x, enc_W, enc_b, zA);

    float* zin = zA;
    float* zout = zB;
    for (int i = 0; i < NL; i++) {
        int has_bn = (i < NL - 1);
        k_agg<<<(NN * 32 + TB - 1) / TB, TB>>>(zin, i > 0);
        if (has_bn) {
            cudaMemsetAsync(pbnsum, 0, HH * sizeof(float));
            cudaMemsetAsync(pbnsq, 0, HH * sizeof(float));
        }
        k_gemm_mma<<<NTILES, 512, GEMM_SMEM>>>(
            Wth + (size_t)(2 * i + 0) * HH * HH, Wtl + (size_t)(2 * i + 0) * HH * HH,
            Wth + (size_t)(2 * i + 1) * HH * HH, Wtl + (size_t)(2 * i + 1) * HH * HH,
            b + (size_t)i * HH, zout, has_bn);
        if (has_bn) {
            k_bnfin<<<1, HH>>>(bng + (size_t)i * HH, bnb + (size_t)i * HH);
            k_bnapply<<<(NN * (HH / 4) + TB - 1) / TB, TB>>>(zout);
        }
        float* tmp = zin; zin = zout; zout = tmp;
    }

    k_dec<<<(NN * 32 + TB - 1) / TB, TB>>>(zin, dec_W, dec_b, out);
}